// round 16
// baseline (speedup 1.0000x reference)
#include <cuda_runtime.h>
#include <cuda_bf16.h>
#include <cuda_fp16.h>
#include <cuda_fp8.h>
#include <cstdint>

// Problem constants
#define TT 512
#define DD 2048
#define II 768
#define EE 16
#define KTOP 8

// ---------------- device scratch (no allocations allowed) ----------------
__device__ __align__(16) uint8_t g_x8[TT*DD];            // x quantized e4m3 bytes
__device__ __align__(16) uint8_t g_xsf[TT*(DD/32)];      // x ue8m0 scale exponents
__device__ __half g_act[(size_t)EE*TT*II];               // silu(g)*u  (fp16)
__device__ float g_comb[TT*EE];
__device__ int   g_cnt[EE];
__device__ int   g_tok[EE*TT];

// ---------------- helpers ----------------
__device__ __forceinline__ uint32_t smem_u32(const void* p) {
    return (uint32_t)__cvta_generic_to_shared(p);
}
__device__ __forceinline__ void ldm_x4(uint32_t r[4], const void* p) {
    uint32_t addr = smem_u32(p);
    asm volatile("ldmatrix.sync.aligned.m8n8.x4.shared.b16 {%0,%1,%2,%3}, [%4];"
                 : "=r"(r[0]), "=r"(r[1]), "=r"(r[2]), "=r"(r[3]) : "r"(addr));
}
__device__ __forceinline__ void mma_f16(float c[4], const uint32_t a[4], uint32_t b0, uint32_t b1) {
    asm volatile("mma.sync.aligned.m16n8k16.row.col.f32.f16.f16.f32 "
                 "{%0,%1,%2,%3},{%4,%5,%6,%7},{%8,%9},{%0,%1,%2,%3};"
                 : "+f"(c[0]), "+f"(c[1]), "+f"(c[2]), "+f"(c[3])
                 : "r"(a[0]), "r"(a[1]), "r"(a[2]), "r"(a[3]), "r"(b0), "r"(b1));
}
// fp8 e4m3 MMA m16n8k32, C = 0, D = p
__device__ __forceinline__ void mma_e4m3(float d[4],
                                         uint32_t a0, uint32_t a1, uint32_t a2, uint32_t a3,
                                         uint32_t b0, uint32_t b1) {
    asm volatile("mma.sync.aligned.m16n8k32.row.col.f32.e4m3.e4m3.f32 "
                 "{%0,%1,%2,%3},{%4,%5,%6,%7},{%8,%9},{%10,%11,%12,%13};"
                 : "=f"(d[0]), "=f"(d[1]), "=f"(d[2]), "=f"(d[3])
                 : "r"(a0), "r"(a1), "r"(a2), "r"(a3), "r"(b0), "r"(b1),
                   "f"(0.f), "f"(0.f), "f"(0.f), "f"(0.f));
}
__device__ __forceinline__ uint32_t hmul2u(uint32_t a, uint32_t s) {
    uint32_t d; asm("mul.rn.f16x2 %0,%1,%2;" : "=r"(d) : "r"(a), "r"(s)); return d;
}
__device__ __forceinline__ void cpa16(void* dst, const void* src, int sz) {
    uint32_t d = smem_u32(dst);
    asm volatile("cp.async.cg.shared.global [%0], [%1], 16, %2;" :: "r"(d), "l"(src), "r"(sz));
}
#define CP_COMMIT() asm volatile("cp.async.commit_group;" ::: "memory")
#define CP_WAIT0()  asm volatile("cp.async.wait_group 0;" ::: "memory")

// ---------------- bit helpers ----------------
__device__ __forceinline__ uint32_t nib_sel(uint32_t x) {
    uint32_t y = x | (x >> 4);
    return __byte_perm(y, y, 0x0020);
}
__device__ __forceinline__ uint32_t gb0(uint4 v) {
    uint32_t t0 = __byte_perm(v.x, v.y, 0x0040);
    uint32_t t1 = __byte_perm(v.z, v.w, 0x0040);
    return __byte_perm(t0, t1, 0x5410);
}
// packed fp4 word (4 bytes = 8 values k0..k7) -> 8 e4m3 bytes (exact)
__device__ __forceinline__ void exp8_e4m3(uint32_t p, uint32_t& o0, uint32_t& o1) {
    uint32_t sl = nib_sel(p & 0x07070707u);
    uint32_t sh = nib_sel((p >> 4) & 0x07070707u);
    const uint32_t MA = 0x3C383000u, MB = 0x4C484440u;   // e4m3 mags 0,.5,1,1.5 / 2,3,4,6
    uint32_t ML = __byte_perm(MA, MB, sl) | ((p << 4) & 0x80808080u);  // even k
    uint32_t MH = __byte_perm(MA, MB, sh) | (p & 0x80808080u);         // odd k
    o0 = __byte_perm(ML, MH, 0x5140);   // k0..k3
    o1 = __byte_perm(ML, MH, 0x7362);   // k4..k7
}
// fp4 -> fp16 fragments (gemm2), exact
__device__ __forceinline__ uint32_t tb(uint32_t p0, uint32_t p1, uint32_t p2, uint32_t p3, int q) {
    uint32_t s = (uint32_t)(q | ((q + 4) << 4));
    return __byte_perm(__byte_perm(p0, p1, s), __byte_perm(p2, p3, s), 0x5410);
}
__device__ __forceinline__ uint4 dq8p_fp16(uint32_t p, uint32_t s2) {
    uint32_t sl = nib_sel(p & 0x07070707u);
    uint32_t sh = nib_sel((p >> 4) & 0x07070707u);
    const uint32_t HA = 0x3E3C3800u, HB = 0x46444240u;
    uint32_t Hl = __byte_perm(HA, HB, sl) | ((p << 4) & 0x80808080u);
    uint32_t Hh = __byte_perm(HA, HB, sh) | (p & 0x80808080u);
    uint32_t A0 = __byte_perm(Hl, Hh, 0x5140);
    uint32_t A1 = __byte_perm(Hl, Hh, 0x7362);
    uint4 r;
    r.x = hmul2u(__byte_perm(A0, 0, 0x1404), s2);
    r.y = hmul2u(__byte_perm(A0, 0, 0x3424), s2);
    r.z = hmul2u(__byte_perm(A1, 0, 0x1404), s2);
    r.w = hmul2u(__byte_perm(A1, 0, 0x3424), s2);
    return r;
}

// ---------------- kernel 1: zero out + counters ----------------
__global__ void k_zero(float* __restrict__ out) {
    int i = blockIdx.x * blockDim.x + threadIdx.x;
    if (i < TT*DD) out[i] = 0.f;
    if (i < EE) g_cnt[i] = 0;
}

// ---------------- kernel 2: fp8 quantize x -> e4m3 bytes + ue8m0 exponents ----------------
__global__ void k_quant(const float* __restrict__ x) {
    int gid = blockIdx.x * blockDim.x + threadIdx.x;
    float v = x[gid];
    float a = fabsf(v);
    #pragma unroll
    for (int off = 16; off; off >>= 1) a = fmaxf(a, __shfl_xor_sync(0xFFFFFFFFu, a, off));
    a = fmaxf(a, 0.0001f);
    float scale = a * (1.0f / 448.0f);
    unsigned bits = __float_as_uint(scale);
    unsigned exp = ((bits >> 23) & 255u) + ((bits & 0x7FFFFFu) != 0u);
    exp = min(max(exp, 1u), 254u);
    float rscale = __uint_as_float(exp << 23);
    float inv = 1.0f / rscale;
    __nv_fp8_storage_t q = __nv_cvt_float_to_fp8(v * inv, __NV_SATFINITE, __NV_E4M3);
    g_x8[gid] = (uint8_t)q;
    if ((gid & 31) == 0) g_xsf[gid >> 5] = (uint8_t)exp;
}

// ---------------- kernel 3: routing ----------------
__global__ void k_route(const float* __restrict__ tw, const int* __restrict__ tids) {
    int t = threadIdx.x;   // blockDim = 512
    float c[EE];
    #pragma unroll
    for (int e = 0; e < EE; e++) c[e] = 0.f;
    #pragma unroll
    for (int k = 0; k < KTOP; k++) c[tids[t*KTOP + k]] += tw[t*KTOP + k];
    #pragma unroll
    for (int e = 0; e < EE; e++) {
        g_comb[t*EE + e] = c[e];
        if (c[e] > 0.f) {
            int s = atomicAdd(&g_cnt[e], 1);
            g_tok[e*TT + s] = t;
        }
    }
}

// ---------------- kernel 4: GEMM1 via fp8 mma.sync m16n8k32, scale-folded ----------------
// M=64 tokens, N=64 gate + 64 up, K chunks of 64 (2 k-groups), 128 threads.
__global__ __launch_bounds__(128, 4) void k_gemm1(const int* __restrict__ w13,
                                                  const int* __restrict__ w13s) {
    const int e = blockIdx.z;
    const int cnt = g_cnt[e];
    const int m0 = blockIdx.x * 64;
    if (m0 >= cnt) return;
    const int n0 = blockIdx.y * 64;   // [0, 768)

    __shared__ __align__(16) uint8_t As[2][64][80];      // e4m3 A, pad-80 (conflict-free LDS.32)
    __shared__ __align__(16) uint8_t Bs[2][128][80];     // e4m3 B (gate rows 0-63, up 64-127)
    __shared__ uint8_t sAs[2][2][64];                    // [buf][kg][row] eA exponents
    __shared__ uint8_t sBs[2][2][128];                   // [buf][kg][n] eB exponents
    __shared__ int s_tok[64];

    const int tid = threadIdx.x;
    const int lane = tid & 31, warp = tid >> 5;
    const int q = lane & 3, g4 = lane >> 2;
    const int r8 = tid >> 3, seg8 = tid & 7;             // B loader
    const int ar = tid >> 2, seg4 = tid & 3;             // A loader rows ar, ar+32

    if (tid < 64) {
        int r = m0 + tid;
        s_tok[tid] = (r < cnt) ? g_tok[e*TT + r] : -1;
    }
    __syncthreads();

    const int atok0 = s_tok[ar], atok1 = s_tok[ar + 32];
    const int rgS = e*1536 + (tid >> 6)*768 + n0 + (tid & 63);   // scale row (one per thread)

    float acc[4][2][2][4];   // [mt][mat][tile][c]
    #pragma unroll
    for (int a = 0; a < 4; a++)
        #pragma unroll
        for (int b = 0; b < 2; b++)
            #pragma unroll
            for (int cc = 0; cc < 2; cc++)
                #pragma unroll
                for (int d = 0; d < 4; d++) acc[a][b][cc][d] = 0.f;

    // ---- prefetch chunk 0 ----
    uint32_t bw[8];
    unsigned short saw = 0x7F7F;
    int2 sbw;
    {
        const void* s0 = (atok0 >= 0) ? (const void*)(g_x8 + (size_t)atok0*2048 + seg4*16)
                                      : (const void*)g_x8;
        const void* s1 = (atok1 >= 0) ? (const void*)(g_x8 + (size_t)atok1*2048 + seg4*16)
                                      : (const void*)g_x8;
        cpa16(&As[0][ar][seg4*16],      s0, (atok0 >= 0) ? 16 : 0);
        cpa16(&As[0][ar + 32][seg4*16], s1, (atok1 >= 0) ? 16 : 0);
        CP_COMMIT();
        #pragma unroll
        for (int i = 0; i < 8; ++i) {
            int row = r8 + 16*i;
            int rg = e*1536 + (row >> 6)*768 + n0 + (row & 63);
            bw[i] = gb0(((const uint4*)(w13 + (size_t)rg*1024))[seg8]);
        }
        if (tid < 64) {
            int t = s_tok[tid];
            if (t >= 0) saw = *(const unsigned short*)(g_xsf + (size_t)t*64);
        }
        sbw = *(const int2*)(w13s + (size_t)rgS*64);
    }

    for (int c = 0; c < DD/64; ++c) {
        const int buf = c & 1;
        CP_WAIT0();                                      // A(c) landed
        // store B expanded + scales
        #pragma unroll
        for (int i = 0; i < 8; ++i) {
            int row = r8 + 16*i;
            uint2 o;
            exp8_e4m3(bw[i], o.x, o.y);
            *(uint2*)&Bs[buf][row][seg8*8] = o;
        }
        if (tid < 64) {
            sAs[buf][0][tid] = (uint8_t)(saw & 255);
            sAs[buf][1][tid] = (uint8_t)(saw >> 8);
        }
        sBs[buf][0][tid] = (uint8_t)sbw.x;
        sBs[buf][1][tid] = (uint8_t)sbw.y;
        __syncthreads();

        // prefetch chunk c+1
        if (c + 1 < DD/64) {
            const int k1 = (c + 1) * 64;
            const void* s0 = (atok0 >= 0) ? (const void*)(g_x8 + (size_t)atok0*2048 + k1 + seg4*16)
                                          : (const void*)g_x8;
            const void* s1 = (atok1 >= 0) ? (const void*)(g_x8 + (size_t)atok1*2048 + k1 + seg4*16)
                                          : (const void*)g_x8;
            cpa16(&As[buf^1][ar][seg4*16],      s0, (atok0 >= 0) ? 16 : 0);
            cpa16(&As[buf^1][ar + 32][seg4*16], s1, (atok1 >= 0) ? 16 : 0);
            CP_COMMIT();
            #pragma unroll
            for (int i = 0; i < 8; ++i) {
                int row = r8 + 16*i;
                int rg = e*1536 + (row >> 6)*768 + n0 + (row & 63);
                bw[i] = gb0(((const uint4*)(w13 + (size_t)rg*1024))[(c+1)*8 + seg8]);
            }
            if (tid < 64) {
                int t = s_tok[tid];
                if (t >= 0) saw = *(const unsigned short*)(g_xsf + (size_t)t*64 + (c+1)*2);
            }
            sbw = *(const int2*)(w13s + (size_t)rgS*64 + (c+1)*2);
        }

        // compute chunk c: 2 k-groups of 32
        #pragma unroll
        for (int kg = 0; kg < 2; ++kg) {
            const int koff = kg * 32;
            uint32_t br[2][2][2];
            int ebp[2][2][2];
            #pragma unroll
            for (int mat = 0; mat < 2; ++mat)
                #pragma unroll
                for (int tile = 0; tile < 2; ++tile) {
                    int rowB = mat*64 + warp*16 + tile*8 + g4;
                    br[mat][tile][0] = *(const uint32_t*)&Bs[buf][rowB][koff + 4*q];
                    br[mat][tile][1] = *(const uint32_t*)&Bs[buf][rowB][koff + 16 + 4*q];
                    int nb = mat*64 + warp*16 + tile*8 + 2*q;
                    ebp[mat][tile][0] = ((int)sBs[buf][kg][nb]     << 23) - (127 << 23);
                    ebp[mat][tile][1] = ((int)sBs[buf][kg][nb + 1] << 23) - (127 << 23);
                }
            #pragma unroll
            for (int mt = 0; mt < 4; ++mt) {
                const int rowA = mt*16 + g4;
                uint32_t a0 = *(const uint32_t*)&As[buf][rowA]    [koff + 4*q];
                uint32_t a1 = *(const uint32_t*)&As[buf][rowA + 8][koff + 4*q];
                uint32_t a2 = *(const uint32_t*)&As[buf][rowA]    [koff + 16 + 4*q];
                uint32_t a3 = *(const uint32_t*)&As[buf][rowA + 8][koff + 16 + 4*q];
                int ea0 = (int)sAs[buf][kg][rowA]     << 23;
                int ea1 = (int)sAs[buf][kg][rowA + 8] << 23;
                #pragma unroll
                for (int mat = 0; mat < 2; ++mat)
                    #pragma unroll
                    for (int tile = 0; tile < 2; ++tile) {
                        float p[4];
                        mma_e4m3(p, a0, a1, a2, a3, br[mat][tile][0], br[mat][tile][1]);
                        acc[mt][mat][tile][0] += __uint_as_float((uint32_t)(ea0 + ebp[mat][tile][0])) * p[0];
                        acc[mt][mat][tile][1] += __uint_as_float((uint32_t)(ea0 + ebp[mat][tile][1])) * p[1];
                        acc[mt][mat][tile][2] += __uint_as_float((uint32_t)(ea1 + ebp[mat][tile][0])) * p[2];
                        acc[mt][mat][tile][3] += __uint_as_float((uint32_t)(ea1 + ebp[mat][tile][1])) * p[3];
                    }
            }
        }
        __syncthreads();
    }

    // ---- epilogue: silu(gate)*up -> fp16 act ----
    const size_t abase = ((size_t)e*TT + m0) * II + n0;
    #pragma unroll
    for (int mt = 0; mt < 4; ++mt)
        #pragma unroll
        for (int tile = 0; tile < 2; ++tile)
            #pragma unroll
            for (int h = 0; h < 2; ++h) {
                int row = mt*16 + g4 + 8*h;
                int col = warp*16 + tile*8 + 2*q;
                float g0 = acc[mt][0][tile][2*h + 0], g1 = acc[mt][0][tile][2*h + 1];
                float u0 = acc[mt][1][tile][2*h + 0], u1 = acc[mt][1][tile][2*h + 1];
                float a0 = (g0 / (1.f + __expf(-g0))) * u0;
                float a1 = (g1 / (1.f + __expf(-g1))) * u1;
                *(__half2*)(g_act + abase + (size_t)row*II + col) = __floats2half2_rn(a0, a1);
            }
}

// ---------------- kernel 5: GEMM2 (a @ W2^T) mma.sync fp16 (proven R10) ----------------
__global__ __launch_bounds__(128, 4) void k_gemm2(const int* __restrict__ w2,
                                                  const int* __restrict__ w2s,
                                                  float* __restrict__ out) {
    const int e = blockIdx.z;
    const int cnt = g_cnt[e];
    const int m0 = blockIdx.x * 64;
    if (m0 >= cnt) return;
    const int n0 = blockIdx.y * 64;   // [0, 2048)

    __shared__ __align__(16) __half As[2][64][72];
    __shared__ uint32_t Bp[2][64][12];
    __shared__ int s_tok[64];

    const int tid = threadIdx.x;
    const int lane = tid & 31, warp = tid >> 5;
    const int q = lane & 3, g4 = lane >> 2;
    const int rbase = tid >> 3, seg = tid & 7;

    if (tid < 64) {
        int r = m0 + tid;
        s_tok[tid] = (r < cnt) ? g_tok[e*TT + r] : -1;
    }
    __syncthreads();

    const __half* arow = g_act + ((size_t)e*TT + m0) * II;
    const int* sptr = (tid < 64) ? (w2s + (size_t)(e*DD + n0 + tid) * (II/32)) : 0;

    float acc[4][2][4];
    #pragma unroll
    for (int a = 0; a < 4; a++)
        #pragma unroll
        for (int b = 0; b < 2; b++)
            #pragma unroll
            for (int c = 0; c < 4; c++) acc[a][b][c] = 0.f;

    uint32_t bw[4];
    uint2 s2w = make_uint2(0, 0);
    #pragma unroll
    for (int i = 0; i < 4; ++i)
        cpa16(&As[0][rbase + 16*i][seg*8], arow + (size_t)(rbase + 16*i)*II + seg*8, 16);
    CP_COMMIT();
    #pragma unroll
    for (int i = 0; i < 4; ++i) {
        int rowg = e*DD + n0 + rbase + 16*i;
        bw[i] = gb0(*((const uint4*)(w2 + (size_t)rowg * (II/2)) + seg));
    }
    if (tid < 64) {
        int2 sf = *(const int2*)(sptr);
        s2w.x = (uint32_t)((sf.x - 112) << 10) * 0x10001u;
        s2w.y = (uint32_t)((sf.y - 112) << 10) * 0x10001u;
    }

    for (int c = 0; c < II/64; ++c) {
        const int buf = c & 1;
        CP_WAIT0();
        #pragma unroll
        for (int i = 0; i < 4; ++i) Bp[buf][rbase + 16*i][seg] = bw[i];
        if (tid < 64) {
            Bp[buf][tid][8] = s2w.x;
            Bp[buf][tid][9] = s2w.y;
        }
        __syncthreads();

        if (c + 1 < II/64) {
            #pragma unroll
            for (int i = 0; i < 4; ++i)
                cpa16(&As[buf^1][rbase + 16*i][seg*8],
                      arow + (size_t)(rbase + 16*i)*II + (c+1)*64 + seg*8, 16);
            CP_COMMIT();
            #pragma unroll
            for (int i = 0; i < 4; ++i) {
                int rowg = e*DD + n0 + rbase + 16*i;
                bw[i] = gb0(*((const uint4*)(w2 + (size_t)rowg * (II/2)) + (c+1)*8 + seg));
            }
            if (tid < 64) {
                int2 sf = *(const int2*)(sptr + 2*(c+1));
                s2w.x = (uint32_t)((sf.x - 112) << 10) * 0x10001u;
                s2w.y = (uint32_t)((sf.y - 112) << 10) * 0x10001u;
            }
        }

        #pragma unroll
        for (int kb = 0; kb < 2; ++kb) {
            uint4 bb[2];
            #pragma unroll
            for (int nc = 0; nc < 2; ++nc) {
                const int rowB = warp*16 + nc*8 + g4;
                uint4 wb = *(uint4*)&Bp[buf][rowB][4*kb];
                uint32_t sbb = Bp[buf][rowB][8 + kb];
                bb[nc] = dq8p_fp16(tb(wb.x, wb.y, wb.z, wb.w, q), sbb);
            }
            #pragma unroll
            for (int kh = 0; kh < 2; ++kh) {
                #pragma unroll
                for (int mt = 0; mt < 4; ++mt) {
                    uint32_t af[4];
                    ldm_x4(af, &As[buf][mt*16 + (lane & 15)][kb*32 + kh*16 + ((lane >> 4) << 3)]);
                    #pragma unroll
                    for (int nc = 0; nc < 2; ++nc) {
                        if (kh == 0) mma_f16(acc[mt][nc], af, bb[nc].x, bb[nc].y);
                        else         mma_f16(acc[mt][nc], af, bb[nc].z, bb[nc].w);
                    }
                }
            }
        }
        __syncthreads();
    }

    #pragma unroll
    for (int mt = 0; mt < 4; ++mt)
        #pragma unroll
        for (int nc = 0; nc < 2; ++nc)
            #pragma unroll
            for (int rp = 0; rp < 2; ++rp) {
                int row = mt*16 + (lane >> 2) + rp*8;
                if (m0 + row < cnt) {
                    int t = s_tok[row];
                    float cv = g_comb[t*EE + e];
                    int col = n0 + warp*16 + nc*8 + ((lane & 3) << 1);
                    atomicAdd(&out[(size_t)t*DD + col + 0], cv * acc[mt][nc][rp*2+0]);
                    atomicAdd(&out[(size_t)t*DD + col + 1], cv * acc[mt][nc][rp*2+1]);
                }
            }
}

// ---------------- launcher ----------------
extern "C" void kernel_launch(void* const* d_in, const int* in_sizes, int n_in,
                              void* d_out, int out_size) {
    const float* hs   = (const float*)d_in[0];
    const float* tw   = (const float*)d_in[1];
    const int*   tids = (const int*)d_in[2];
    const int*   w13  = (const int*)d_in[3];
    const int*   w13s = (const int*)d_in[4];
    const int*   w2   = (const int*)d_in[5];
    const int*   w2s  = (const int*)d_in[6];
    float* out = (float*)d_out;

    k_zero<<<(TT*DD + 255)/256, 256>>>(out);
    k_quant<<<(TT*DD + 255)/256, 256>>>(hs);
    k_route<<<1, TT>>>(tw, tids);
    {
        dim3 g1(TT/64, II/64, EE);      // (8, 12, 16)
        k_gemm1<<<g1, 128>>>(w13, w13s);
        dim3 g2(TT/64, DD/64, EE);      // (8, 32, 16)
        k_gemm2<<<g2, 128>>>(w2, w2s, out);
    }
    (void)in_sizes; (void)n_in; (void)out_size;
}